// round 5
// baseline (speedup 1.0000x reference)
#include <cuda_runtime.h>
#include <cuda_bf16.h>

#define FEATS 64
#define MAX_NODES 100000
#define MAX_EDGES 1000000

// ---- scratch (__device__ globals; no allocs allowed) ----
__device__ float g_sum[(size_t)MAX_NODES * FEATS];   // raw neighbor sums
__device__ float g_deg[MAX_NODES];                   // degree (float, for out_kernel)
__device__ int   g_count[MAX_NODES];                 // degree (int)
__device__ int   g_start[MAX_NODES];                 // CSR row start
__device__ int   g_cursor[MAX_NODES];                // fill cursor
__device__ int   g_edge_src[MAX_EDGES];              // src sorted by dst

// ---------------------------------------------------------------------------
// packed f32x2 FMA (sm_103a FFMA2)
// ---------------------------------------------------------------------------
__device__ __forceinline__ unsigned long long fma2(unsigned long long a,
                                                   unsigned long long b,
                                                   unsigned long long c) {
    unsigned long long d;
    asm("fma.rn.f32x2 %0, %1, %2, %3;" : "=l"(d) : "l"(a), "l"(b), "l"(c));
    return d;
}

// ---------------------------------------------------------------------------
// 1) zero int degree counters
// ---------------------------------------------------------------------------
__global__ void zero_counts(int n_nodes) {
    int i = blockIdx.x * blockDim.x + threadIdx.x;
    if (i < n_nodes) g_count[i] = 0;
}

// ---------------------------------------------------------------------------
// 2) histogram of dst
// ---------------------------------------------------------------------------
__global__ void hist_kernel(const int* __restrict__ dst, int n_edges) {
    int e = blockIdx.x * blockDim.x + threadIdx.x;
    if (e < n_edges) atomicAdd(&g_count[dst[e]], 1);
}

// ---------------------------------------------------------------------------
// 3) exclusive scan: ONE block, 1024 threads, serial chunk per thread.
//    All __syncthreads are uniform (no divergence possible).
// ---------------------------------------------------------------------------
__global__ __launch_bounds__(1024) void scan_kernel(int n_nodes) {
    __shared__ int s[1024];
    int t = threadIdx.x;
    int chunk = (n_nodes + 1023) / 1024;
    int lo = t * chunk;
    int hi = lo + chunk; if (hi > n_nodes) hi = n_nodes;
    int sum = 0;
    for (int i = lo; i < hi; i++) sum += g_count[i];
    s[t] = sum;
    __syncthreads();
    #pragma unroll
    for (int off = 1; off < 1024; off <<= 1) {
        int v = (t >= off) ? s[t - off] : 0;
        __syncthreads();
        s[t] += v;
        __syncthreads();
    }
    int base = s[t] - sum;   // exclusive prefix for this chunk
    for (int i = lo; i < hi; i++) {
        g_start[i]  = base;
        g_cursor[i] = base;
        base += g_count[i];
    }
}

// ---------------------------------------------------------------------------
// 4) reorder: bin src indices by dst
// ---------------------------------------------------------------------------
__global__ void reorder_kernel(const int* __restrict__ src,
                               const int* __restrict__ dst, int n_edges) {
    int e = blockIdx.x * blockDim.x + threadIdx.x;
    if (e < n_edges) {
        int p = atomicAdd(&g_cursor[dst[e]], 1);
        g_edge_src[p] = src[e];
    }
}

// ---------------------------------------------------------------------------
// 5) gather: one warp per node (all 32 lanes share node -> safe full-mask shfl).
//    Writes RAW sums to g_sum and degree to g_deg (same contract as atomics).
// ---------------------------------------------------------------------------
__global__ __launch_bounds__(256) void gather_kernel(const float* __restrict__ x,
                                                     int n_nodes) {
    int node = (blockIdx.x * blockDim.x + threadIdx.x) >> 5;
    int lane = threadIdx.x & 31;
    if (node >= n_nodes) return;
    int s0  = g_start[node];
    int deg = g_count[node];
    const float2* xb = reinterpret_cast<const float2*>(x);
    float ax = 0.f, ay = 0.f;

    for (int base = 0; base < deg; base += 32) {
        int rem = deg - base;
        int cnt = rem < 32 ? rem : 32;
        int my = (lane < cnt) ? __ldg(&g_edge_src[s0 + base + lane]) : 0;
        int j = 0;
        for (; j + 4 <= cnt; j += 4) {
            int i0 = __shfl_sync(0xffffffffu, my, j);
            int i1 = __shfl_sync(0xffffffffu, my, j + 1);
            int i2 = __shfl_sync(0xffffffffu, my, j + 2);
            int i3 = __shfl_sync(0xffffffffu, my, j + 3);
            float2 v0 = __ldg(&xb[(size_t)i0 * 32 + lane]);
            float2 v1 = __ldg(&xb[(size_t)i1 * 32 + lane]);
            float2 v2 = __ldg(&xb[(size_t)i2 * 32 + lane]);
            float2 v3 = __ldg(&xb[(size_t)i3 * 32 + lane]);
            ax += v0.x + v1.x + v2.x + v3.x;
            ay += v0.y + v1.y + v2.y + v3.y;
        }
        for (; j < cnt; j++) {
            int i0 = __shfl_sync(0xffffffffu, my, j);
            float2 v = __ldg(&xb[(size_t)i0 * 32 + lane]);
            ax += v.x;  ay += v.y;
        }
    }
    float2 r;  r.x = ax;  r.y = ay;
    reinterpret_cast<float2*>(g_sum)[(size_t)node * 32 + lane] = r;
    if (lane == 0) g_deg[node] = (float)deg;
}

// ---------------------------------------------------------------------------
// 6) out = relu(x@Ws + (sum/max(deg,1))@Wn + b)   — VERBATIM round-4 kernel
// ---------------------------------------------------------------------------
#define SA2_STRIDE 65
#define SMEM_A_BYTES (64 * SA2_STRIDE * 8)                 // 33280
#define SMEM_TOTAL (SMEM_A_BYTES + 2 * 16384 + 512)        // 66560

__global__ __launch_bounds__(256) void out_kernel(const float* __restrict__ x,
                                                  const float* __restrict__ Ws,
                                                  const float* __restrict__ Wn,
                                                  const float* __restrict__ b,
                                                  float* __restrict__ out,
                                                  int n_rows) {
    extern __shared__ char smem[];
    float2* sA2 = reinterpret_cast<float2*>(smem);
    float4* sWs = reinterpret_cast<float4*>(smem + SMEM_A_BYTES);
    float4* sWn = reinterpret_cast<float4*>(smem + SMEM_A_BYTES + 16384);
    float*  sb   = reinterpret_cast<float*>(smem + SMEM_A_BYTES + 32768);
    float*  sinv = sb + 64;

    int tid  = threadIdx.x;
    int row0 = blockIdx.x * 64;

    {
        const float4* gWs = reinterpret_cast<const float4*>(Ws);
        const float4* gWn = reinterpret_cast<const float4*>(Wn);
        #pragma unroll
        for (int i = 0; i < 4; i++) {
            int idx = tid + 256 * i;
            sWs[idx] = __ldg(&gWs[idx]);
            sWn[idx] = __ldg(&gWn[idx]);
        }
        if (tid < FEATS) sb[tid] = b[tid];
        if (tid < 64) {
            int r = row0 + tid;
            float dg = (r < n_rows) ? g_deg[r] : 1.0f;
            sinv[tid] = 1.0f / fmaxf(dg, 1.0f);
        }
    }

    {
        const float4* gx = reinterpret_cast<const float4*>(x);
        #pragma unroll
        for (int i = 0; i < 4; i++) {
            int idx = tid + 256 * i;
            int r = idx >> 4, c = idx & 15;
            int grow = row0 + r;
            float4 v = make_float4(0.f, 0.f, 0.f, 0.f);
            if (grow < n_rows) v = __ldg(&gx[(size_t)grow * 16 + c]);
            float2* dstp = &sA2[r * SA2_STRIDE + c * 4];
            dstp[0] = make_float2(v.x, v.x);
            dstp[1] = make_float2(v.y, v.y);
            dstp[2] = make_float2(v.z, v.z);
            dstp[3] = make_float2(v.w, v.w);
        }
    }
    __syncthreads();

    int ty = tid >> 4;
    int tx = tid & 15;

    unsigned long long acc[4][2];
    #pragma unroll
    for (int r = 0; r < 4; r++) { acc[r][0] = 0ull; acc[r][1] = 0ull; }

    const unsigned long long* a0p =
        reinterpret_cast<const unsigned long long*>(&sA2[(ty * 4 + 0) * SA2_STRIDE]);
    const unsigned long long* a1p = a0p + SA2_STRIDE;
    const unsigned long long* a2p = a1p + SA2_STRIDE;
    const unsigned long long* a3p = a2p + SA2_STRIDE;

    #pragma unroll 16
    for (int k = 0; k < FEATS; k++) {
        ulonglong2 w = *reinterpret_cast<const ulonglong2*>(&sWs[k * 16 + tx]);
        unsigned long long a0 = a0p[k], a1 = a1p[k], a2 = a2p[k], a3 = a3p[k];
        acc[0][0] = fma2(a0, w.x, acc[0][0]);  acc[0][1] = fma2(a0, w.y, acc[0][1]);
        acc[1][0] = fma2(a1, w.x, acc[1][0]);  acc[1][1] = fma2(a1, w.y, acc[1][1]);
        acc[2][0] = fma2(a2, w.x, acc[2][0]);  acc[2][1] = fma2(a2, w.y, acc[2][1]);
        acc[3][0] = fma2(a3, w.x, acc[3][0]);  acc[3][1] = fma2(a3, w.y, acc[3][1]);
    }
    __syncthreads();

    {
        const float4* gs = reinterpret_cast<const float4*>(g_sum);
        #pragma unroll
        for (int i = 0; i < 4; i++) {
            int idx = tid + 256 * i;
            int r = idx >> 4, c = idx & 15;
            int grow = row0 + r;
            float4 v = make_float4(0.f, 0.f, 0.f, 0.f);
            if (grow < n_rows) {
                v = gs[(size_t)grow * 16 + c];
                float inv = sinv[r];
                v.x *= inv; v.y *= inv; v.z *= inv; v.w *= inv;
            }
            float2* dstp = &sA2[r * SA2_STRIDE + c * 4];
            dstp[0] = make_float2(v.x, v.x);
            dstp[1] = make_float2(v.y, v.y);
            dstp[2] = make_float2(v.z, v.z);
            dstp[3] = make_float2(v.w, v.w);
        }
    }
    __syncthreads();

    #pragma unroll 16
    for (int k = 0; k < FEATS; k++) {
        ulonglong2 w = *reinterpret_cast<const ulonglong2*>(&sWn[k * 16 + tx]);
        unsigned long long a0 = a0p[k], a1 = a1p[k], a2 = a2p[k], a3 = a3p[k];
        acc[0][0] = fma2(a0, w.x, acc[0][0]);  acc[0][1] = fma2(a0, w.y, acc[0][1]);
        acc[1][0] = fma2(a1, w.x, acc[1][0]);  acc[1][1] = fma2(a1, w.y, acc[1][1]);
        acc[2][0] = fma2(a2, w.x, acc[2][0]);  acc[2][1] = fma2(a2, w.y, acc[2][1]);
        acc[3][0] = fma2(a3, w.x, acc[3][0]);  acc[3][1] = fma2(a3, w.y, acc[3][1]);
    }

    float4 bb = reinterpret_cast<const float4*>(sb)[tx];
    float4* out4 = reinterpret_cast<float4*>(out);
    #pragma unroll
    for (int r = 0; r < 4; r++) {
        int row = row0 + ty * 4 + r;
        if (row < n_rows) {
            float2 p01 = *reinterpret_cast<float2*>(&acc[r][0]);
            float2 p23 = *reinterpret_cast<float2*>(&acc[r][1]);
            float4 o;
            o.x = fmaxf(p01.x + bb.x, 0.f);
            o.y = fmaxf(p01.y + bb.y, 0.f);
            o.z = fmaxf(p23.x + bb.z, 0.f);
            o.w = fmaxf(p23.y + bb.w, 0.f);
            out4[(size_t)row * 16 + tx] = o;
        }
    }
}

// ---------------------------------------------------------------------------
// Launch. Inputs: x f32[100000,64], W_self f32[64,64], W_neigh f32[64,64],
//                 b f32[64], src i32[1e6], dst i32[1e6], num_dst scalar
// ---------------------------------------------------------------------------
extern "C" void kernel_launch(void* const* d_in, const int* in_sizes, int n_in,
                              void* d_out, int out_size) {
    const float* x   = (const float*)d_in[0];
    const float* Ws  = (const float*)d_in[1];
    const float* Wn  = (const float*)d_in[2];
    const float* b   = (const float*)d_in[3];
    const int*   src = (const int*)d_in[4];
    const int*   dst = (const int*)d_in[5];
    float* out = (float*)d_out;

    int n_edges = in_sizes[4];
    if (n_edges > MAX_EDGES) n_edges = MAX_EDGES;
    int n_rows = out_size / FEATS;
    if (n_rows > MAX_NODES) n_rows = MAX_NODES;

    int nb_nodes = (n_rows + 255) / 256;
    int nb_edges = (n_edges + 255) / 256;

    zero_counts<<<nb_nodes, 256>>>(n_rows);
    hist_kernel<<<nb_edges, 256>>>(dst, n_edges);
    scan_kernel<<<1, 1024>>>(n_rows);
    reorder_kernel<<<nb_edges, 256>>>(src, dst, n_edges);

    {
        long long threads_total = (long long)n_rows * 32;
        int blocks = (int)((threads_total + 255) / 256);
        gather_kernel<<<blocks, 256>>>(x, n_rows);
    }

    {
        static int smem_set = 0;
        if (!smem_set) {
            cudaFuncSetAttribute(out_kernel,
                                 cudaFuncAttributeMaxDynamicSharedMemorySize,
                                 SMEM_TOTAL);
            smem_set = 1;
        }
        int blocks = (n_rows + 63) / 64;
        out_kernel<<<blocks, 256, SMEM_TOTAL>>>(x, Ws, Wn, b, out, n_rows);
    }
}

// round 6
// speedup vs baseline: 2.4015x; 2.4015x over previous
#include <cuda_runtime.h>
#include <cuda_bf16.h>

#define FEATS 64
#define MAX_NODES 100000
#define MAX_EDGES 1000000
#define SCAN_BLK 1024

// ---- scratch (__device__ globals; no allocs allowed) ----
__device__ float g_sum[(size_t)MAX_NODES * FEATS];   // raw neighbor sums
__device__ float g_deg[MAX_NODES];                   // degree (float)
__device__ int   g_count[MAX_NODES];                 // degree (int)
__device__ int   g_incl[MAX_NODES];                  // block-inclusive scan
__device__ int   g_start[MAX_NODES];                 // CSR row start
__device__ int   g_cursor[MAX_NODES];                // fill cursor
__device__ int   g_blocksums[128];
__device__ int   g_edge_src[MAX_EDGES];              // src sorted by dst

// ---------------------------------------------------------------------------
// packed f32x2 FMA (sm_103a FFMA2)
// ---------------------------------------------------------------------------
__device__ __forceinline__ unsigned long long fma2(unsigned long long a,
                                                   unsigned long long b,
                                                   unsigned long long c) {
    unsigned long long d;
    asm("fma.rn.f32x2 %0, %1, %2, %3;" : "=l"(d) : "l"(a), "l"(b), "l"(c));
    return d;
}

// ---------------------------------------------------------------------------
// 1) zero int degree counters
// ---------------------------------------------------------------------------
__global__ void zero_counts(int n_nodes) {
    int i = blockIdx.x * blockDim.x + threadIdx.x;
    if (i < n_nodes) g_count[i] = 0;
}

// ---------------------------------------------------------------------------
// 2) histogram of dst
// ---------------------------------------------------------------------------
__global__ void hist_kernel(const int* __restrict__ dst, int n_edges) {
    int e = blockIdx.x * blockDim.x + threadIdx.x;
    if (e < n_edges) atomicAdd(&g_count[dst[e]], 1);
}

// ---------------------------------------------------------------------------
// 3a) coalesced per-block (1024) inclusive scan + block totals
// ---------------------------------------------------------------------------
__global__ __launch_bounds__(SCAN_BLK) void scan1(int n_nodes) {
    __shared__ int s[SCAN_BLK];
    int i = blockIdx.x * SCAN_BLK + threadIdx.x;     // coalesced
    int v = (i < n_nodes) ? g_count[i] : 0;
    s[threadIdx.x] = v;
    __syncthreads();
    #pragma unroll
    for (int off = 1; off < SCAN_BLK; off <<= 1) {
        int t = (threadIdx.x >= off) ? s[threadIdx.x - off] : 0;
        __syncthreads();
        s[threadIdx.x] += t;
        __syncthreads();
    }
    if (i < n_nodes) g_incl[i] = s[threadIdx.x];
    if (threadIdx.x == SCAN_BLK - 1) g_blocksums[blockIdx.x] = s[SCAN_BLK - 1];
}

// ---------------------------------------------------------------------------
// 3b) exclusive scan of block totals (1 block, 128 threads; nb <= 128)
// ---------------------------------------------------------------------------
__global__ __launch_bounds__(128) void scan2(int nb) {
    __shared__ int s[128];
    int v = (threadIdx.x < nb) ? g_blocksums[threadIdx.x] : 0;
    s[threadIdx.x] = v;
    __syncthreads();
    #pragma unroll
    for (int off = 1; off < 128; off <<= 1) {
        int t = (threadIdx.x >= off) ? s[threadIdx.x - off] : 0;
        __syncthreads();
        s[threadIdx.x] += t;
        __syncthreads();
    }
    if (threadIdx.x < nb) g_blocksums[threadIdx.x] = s[threadIdx.x] - v;  // exclusive
}

// ---------------------------------------------------------------------------
// 3c) finalize exclusive row starts + cursors (coalesced)
// ---------------------------------------------------------------------------
__global__ void scan3(int n_nodes) {
    int i = blockIdx.x * blockDim.x + threadIdx.x;
    if (i < n_nodes) {
        int st = g_incl[i] - g_count[i] + g_blocksums[i / SCAN_BLK];
        g_start[i]  = st;
        g_cursor[i] = st;
    }
}

// ---------------------------------------------------------------------------
// 4) reorder: bin src indices by dst
// ---------------------------------------------------------------------------
__global__ void reorder_kernel(const int* __restrict__ src,
                               const int* __restrict__ dst, int n_edges) {
    int e = blockIdx.x * blockDim.x + threadIdx.x;
    if (e < n_edges) {
        int p = atomicAdd(&g_cursor[dst[e]], 1);
        g_edge_src[p] = src[e];
    }
}

// ---------------------------------------------------------------------------
// 5) gather v2: 16-lane group per node, float4 rows, NO shfl.
//    Indices read via uniform broadcast __ldg (L1-hot); unroll-4 => 4 rows in
//    flight per group, 8 per warp.
// ---------------------------------------------------------------------------
__global__ __launch_bounds__(256) void gather_kernel(const float* __restrict__ x,
                                                     int n_nodes) {
    int grp  = (blockIdx.x * blockDim.x + threadIdx.x) >> 4;   // node
    int lane = threadIdx.x & 15;
    if (grp >= n_nodes) return;
    int s0  = g_start[grp];
    int deg = g_count[grp];
    const float4* x4 = reinterpret_cast<const float4*>(x);
    float4 acc = make_float4(0.f, 0.f, 0.f, 0.f);

    int j = 0;
    for (; j + 4 <= deg; j += 4) {
        int i0 = __ldg(&g_edge_src[s0 + j + 0]);
        int i1 = __ldg(&g_edge_src[s0 + j + 1]);
        int i2 = __ldg(&g_edge_src[s0 + j + 2]);
        int i3 = __ldg(&g_edge_src[s0 + j + 3]);
        float4 v0 = __ldg(&x4[(size_t)i0 * 16 + lane]);
        float4 v1 = __ldg(&x4[(size_t)i1 * 16 + lane]);
        float4 v2 = __ldg(&x4[(size_t)i2 * 16 + lane]);
        float4 v3 = __ldg(&x4[(size_t)i3 * 16 + lane]);
        acc.x += v0.x + v1.x + v2.x + v3.x;
        acc.y += v0.y + v1.y + v2.y + v3.y;
        acc.z += v0.z + v1.z + v2.z + v3.z;
        acc.w += v0.w + v1.w + v2.w + v3.w;
    }
    for (; j < deg; j++) {
        int i0 = __ldg(&g_edge_src[s0 + j]);
        float4 v = __ldg(&x4[(size_t)i0 * 16 + lane]);
        acc.x += v.x;  acc.y += v.y;  acc.z += v.z;  acc.w += v.w;
    }
    reinterpret_cast<float4*>(g_sum)[(size_t)grp * 16 + lane] = acc;
    if (lane == 0) g_deg[grp] = (float)deg;
}

// ---------------------------------------------------------------------------
// 6) out = relu(x@Ws + (sum/max(deg,1))@Wn + b)   — verbatim round-4 kernel
// ---------------------------------------------------------------------------
#define SA2_STRIDE 65
#define SMEM_A_BYTES (64 * SA2_STRIDE * 8)                 // 33280
#define SMEM_TOTAL (SMEM_A_BYTES + 2 * 16384 + 512)        // 66560

__global__ __launch_bounds__(256) void out_kernel(const float* __restrict__ x,
                                                  const float* __restrict__ Ws,
                                                  const float* __restrict__ Wn,
                                                  const float* __restrict__ b,
                                                  float* __restrict__ out,
                                                  int n_rows) {
    extern __shared__ char smem[];
    float2* sA2 = reinterpret_cast<float2*>(smem);
    float4* sWs = reinterpret_cast<float4*>(smem + SMEM_A_BYTES);
    float4* sWn = reinterpret_cast<float4*>(smem + SMEM_A_BYTES + 16384);
    float*  sb   = reinterpret_cast<float*>(smem + SMEM_A_BYTES + 32768);
    float*  sinv = sb + 64;

    int tid  = threadIdx.x;
    int row0 = blockIdx.x * 64;

    {
        const float4* gWs = reinterpret_cast<const float4*>(Ws);
        const float4* gWn = reinterpret_cast<const float4*>(Wn);
        #pragma unroll
        for (int i = 0; i < 4; i++) {
            int idx = tid + 256 * i;
            sWs[idx] = __ldg(&gWs[idx]);
            sWn[idx] = __ldg(&gWn[idx]);
        }
        if (tid < FEATS) sb[tid] = b[tid];
        if (tid < 64) {
            int r = row0 + tid;
            float dg = (r < n_rows) ? g_deg[r] : 1.0f;
            sinv[tid] = 1.0f / fmaxf(dg, 1.0f);
        }
    }

    {
        const float4* gx = reinterpret_cast<const float4*>(x);
        #pragma unroll
        for (int i = 0; i < 4; i++) {
            int idx = tid + 256 * i;
            int r = idx >> 4, c = idx & 15;
            int grow = row0 + r;
            float4 v = make_float4(0.f, 0.f, 0.f, 0.f);
            if (grow < n_rows) v = __ldg(&gx[(size_t)grow * 16 + c]);
            float2* dstp = &sA2[r * SA2_STRIDE + c * 4];
            dstp[0] = make_float2(v.x, v.x);
            dstp[1] = make_float2(v.y, v.y);
            dstp[2] = make_float2(v.z, v.z);
            dstp[3] = make_float2(v.w, v.w);
        }
    }
    __syncthreads();

    int ty = tid >> 4;
    int tx = tid & 15;

    unsigned long long acc[4][2];
    #pragma unroll
    for (int r = 0; r < 4; r++) { acc[r][0] = 0ull; acc[r][1] = 0ull; }

    const unsigned long long* a0p =
        reinterpret_cast<const unsigned long long*>(&sA2[(ty * 4 + 0) * SA2_STRIDE]);
    const unsigned long long* a1p = a0p + SA2_STRIDE;
    const unsigned long long* a2p = a1p + SA2_STRIDE;
    const unsigned long long* a3p = a2p + SA2_STRIDE;

    #pragma unroll 16
    for (int k = 0; k < FEATS; k++) {
        ulonglong2 w = *reinterpret_cast<const ulonglong2*>(&sWs[k * 16 + tx]);
        unsigned long long a0 = a0p[k], a1 = a1p[k], a2 = a2p[k], a3 = a3p[k];
        acc[0][0] = fma2(a0, w.x, acc[0][0]);  acc[0][1] = fma2(a0, w.y, acc[0][1]);
        acc[1][0] = fma2(a1, w.x, acc[1][0]);  acc[1][1] = fma2(a1, w.y, acc[1][1]);
        acc[2][0] = fma2(a2, w.x, acc[2][0]);  acc[2][1] = fma2(a2, w.y, acc[2][1]);
        acc[3][0] = fma2(a3, w.x, acc[3][0]);  acc[3][1] = fma2(a3, w.y, acc[3][1]);
    }
    __syncthreads();

    {
        const float4* gs = reinterpret_cast<const float4*>(g_sum);
        #pragma unroll
        for (int i = 0; i < 4; i++) {
            int idx = tid + 256 * i;
            int r = idx >> 4, c = idx & 15;
            int grow = row0 + r;
            float4 v = make_float4(0.f, 0.f, 0.f, 0.f);
            if (grow < n_rows) {
                v = gs[(size_t)grow * 16 + c];
                float inv = sinv[r];
                v.x *= inv; v.y *= inv; v.z *= inv; v.w *= inv;
            }
            float2* dstp = &sA2[r * SA2_STRIDE + c * 4];
            dstp[0] = make_float2(v.x, v.x);
            dstp[1] = make_float2(v.y, v.y);
            dstp[2] = make_float2(v.z, v.z);
            dstp[3] = make_float2(v.w, v.w);
        }
    }
    __syncthreads();

    #pragma unroll 16
    for (int k = 0; k < FEATS; k++) {
        ulonglong2 w = *reinterpret_cast<const ulonglong2*>(&sWn[k * 16 + tx]);
        unsigned long long a0 = a0p[k], a1 = a1p[k], a2 = a2p[k], a3 = a3p[k];
        acc[0][0] = fma2(a0, w.x, acc[0][0]);  acc[0][1] = fma2(a0, w.y, acc[0][1]);
        acc[1][0] = fma2(a1, w.x, acc[1][0]);  acc[1][1] = fma2(a1, w.y, acc[1][1]);
        acc[2][0] = fma2(a2, w.x, acc[2][0]);  acc[2][1] = fma2(a2, w.y, acc[2][1]);
        acc[3][0] = fma2(a3, w.x, acc[3][0]);  acc[3][1] = fma2(a3, w.y, acc[3][1]);
    }

    float4 bb = reinterpret_cast<const float4*>(sb)[tx];
    float4* out4 = reinterpret_cast<float4*>(out);
    #pragma unroll
    for (int r = 0; r < 4; r++) {
        int row = row0 + ty * 4 + r;
        if (row < n_rows) {
            float2 p01 = *reinterpret_cast<float2*>(&acc[r][0]);
            float2 p23 = *reinterpret_cast<float2*>(&acc[r][1]);
            float4 o;
            o.x = fmaxf(p01.x + bb.x, 0.f);
            o.y = fmaxf(p01.y + bb.y, 0.f);
            o.z = fmaxf(p23.x + bb.z, 0.f);
            o.w = fmaxf(p23.y + bb.w, 0.f);
            out4[(size_t)row * 16 + tx] = o;
        }
    }
}

// ---------------------------------------------------------------------------
// Launch
// ---------------------------------------------------------------------------
extern "C" void kernel_launch(void* const* d_in, const int* in_sizes, int n_in,
                              void* d_out, int out_size) {
    const float* x   = (const float*)d_in[0];
    const float* Ws  = (const float*)d_in[1];
    const float* Wn  = (const float*)d_in[2];
    const float* b   = (const float*)d_in[3];
    const int*   src = (const int*)d_in[4];
    const int*   dst = (const int*)d_in[5];
    float* out = (float*)d_out;

    int n_edges = in_sizes[4];
    if (n_edges > MAX_EDGES) n_edges = MAX_EDGES;
    int n_rows = out_size / FEATS;
    if (n_rows > MAX_NODES) n_rows = MAX_NODES;

    int nb_nodes = (n_rows + 255) / 256;
    int nb_edges = (n_edges + 255) / 256;
    int nb_scan  = (n_rows + SCAN_BLK - 1) / SCAN_BLK;   // 98 <= 128

    zero_counts<<<nb_nodes, 256>>>(n_rows);
    hist_kernel<<<nb_edges, 256>>>(dst, n_edges);
    scan1<<<nb_scan, SCAN_BLK>>>(n_rows);
    scan2<<<1, 128>>>(nb_scan);
    scan3<<<nb_nodes, 256>>>(n_rows);
    reorder_kernel<<<nb_edges, 256>>>(src, dst, n_edges);

    {
        long long threads_total = (long long)n_rows * 16;
        int blocks = (int)((threads_total + 255) / 256);
        gather_kernel<<<blocks, 256>>>(x, n_rows);
    }

    {
        static int smem_set = 0;
        if (!smem_set) {
            cudaFuncSetAttribute(out_kernel,
                                 cudaFuncAttributeMaxDynamicSharedMemorySize,
                                 SMEM_TOTAL);
            smem_set = 1;
        }
        int blocks = (n_rows + 63) / 64;
        out_kernel<<<blocks, 256, SMEM_TOTAL>>>(x, Ws, Wn, b, out, n_rows);
    }
}